// round 3
// baseline (speedup 1.0000x reference)
#include <cuda_runtime.h>
#include <cstdint>

// ---------------------------------------------------------------------------
// Sparse CNN backbone, fp32. Convs: thread = 2 adjacent rows x SLICE cols,
// all tap weights staged in smem once, no barriers in k-loop.
// ---------------------------------------------------------------------------

#define MAXN2 80000
#define MAXN4 13824
#define STATS_BLOCKS 128

__device__ float g_xc[MAXN2 * 32];
__device__ float g_z1[MAXN2 * 32];
__device__ float g_z2[MAXN2 * 32];
__device__ float g_xt[MAXN2 * 32];
__device__ float g_y[MAXN4 * 64];
__device__ float g_part[STATS_BLOCKS * 64 * 2];
__device__ float g_par[128];

typedef unsigned long long ull;

__device__ __forceinline__ ull pack2(float x) {
    ull r;
    asm("mov.b64 %0, {%1, %1};" : "=l"(r) : "f"(x));
    return r;
}
__device__ __forceinline__ void fma2(ull& d, ull a, ull b) {
    asm("fma.rn.f32x2 %0, %1, %2, %0;" : "+l"(d) : "l"(a), "l"(b));
}

// ---------------------------------------------------------------------------
// Conv: thread handles rows (2t, 2t+1) x SLICE output channels.
// Weight LDS amortized over both rows: LDS:FFMA2 = 1:4.
// ---------------------------------------------------------------------------
template <int CIN, int SLICE>
__global__ __launch_bounds__(256, 2) void conv2_t(
    const float* __restrict__ feats, const float* __restrict__ W,
    const int* __restrict__ in_map, int K, int n_in, int n_out, int COUT,
    float* __restrict__ out) {
    extern __shared__ float sW[];
    const int tid = threadIdx.x;
    const int yoff = blockIdx.y * SLICE;
    constexpr int WV = SLICE / 4;

    const int totalv = 27 * CIN * WV;  // K==27 always here
    for (int i = tid; i < totalv; i += 256) {
        int r = i / WV, c = (i % WV) * 4;
        reinterpret_cast<float4*>(sW)[i] =
            *reinterpret_cast<const float4*>(W + (size_t)r * COUT + yoff + c);
    }
    __syncthreads();

    const int row0 = blockIdx.x * 512 + 2 * tid;
    const int row1 = row0 + 1;
    if (row0 >= n_out) return;
    const bool has1 = row1 < n_out;

    ull A0[SLICE / 2], A1[SLICE / 2];
#pragma unroll
    for (int i = 0; i < SLICE / 2; i++) { A0[i] = 0ull; A1[i] = 0ull; }

    int idx0 = __ldg(&in_map[row0]);
    int idx1 = has1 ? __ldg(&in_map[row1]) : n_in;

    for (int k = 0; k < 27; k++) {
        const int i0 = idx0, i1 = idx1;
        if (k + 1 < 27) {
            const int* mp = in_map + (size_t)(k + 1) * n_out;
            idx0 = __ldg(&mp[row0]);
            idx1 = has1 ? __ldg(&mp[row1]) : n_in;
        }
        const bool v0 = i0 < n_in, v1 = i1 < n_in;
        if (!v0 && !v1) continue;

        const float4* p0 = reinterpret_cast<const float4*>(feats + (size_t)i0 * CIN);
        const float4* p1 = reinterpret_cast<const float4*>(feats + (size_t)i1 * CIN);
        const float* wk = sW + k * CIN * SLICE;

#pragma unroll
        for (int cc = 0; cc < CIN / 8; cc++) {
            float f0[8], f1[8];
            if (v0) {
                float4 a = __ldg(&p0[2 * cc]), b = __ldg(&p0[2 * cc + 1]);
                f0[0] = a.x; f0[1] = a.y; f0[2] = a.z; f0[3] = a.w;
                f0[4] = b.x; f0[5] = b.y; f0[6] = b.z; f0[7] = b.w;
            } else {
#pragma unroll
                for (int j = 0; j < 8; j++) f0[j] = 0.f;
            }
            if (v1) {
                float4 a = __ldg(&p1[2 * cc]), b = __ldg(&p1[2 * cc + 1]);
                f1[0] = a.x; f1[1] = a.y; f1[2] = a.z; f1[3] = a.w;
                f1[4] = b.x; f1[5] = b.y; f1[6] = b.z; f1[7] = b.w;
            } else {
#pragma unroll
                for (int j = 0; j < 8; j++) f1[j] = 0.f;
            }
#pragma unroll
            for (int j = 0; j < 8; j++) {
                ull a0 = pack2(f0[j]);
                ull a1 = pack2(f1[j]);
                const ulonglong2* wr =
                    reinterpret_cast<const ulonglong2*>(wk + (cc * 8 + j) * SLICE);
#pragma unroll
                for (int p = 0; p < SLICE / 4; p++) {
                    ulonglong2 w = wr[p];
                    fma2(A0[2 * p], a0, w.x);
                    fma2(A0[2 * p + 1], a0, w.y);
                    fma2(A1[2 * p], a1, w.x);
                    fma2(A1[2 * p + 1], a1, w.y);
                }
            }
        }
    }

    float r0[SLICE], r1[SLICE];
#pragma unroll
    for (int p = 0; p < SLICE / 2; p++) {
        float2 v = *reinterpret_cast<float2*>(&A0[p]);
        r0[2 * p] = v.x; r0[2 * p + 1] = v.y;
        float2 u = *reinterpret_cast<float2*>(&A1[p]);
        r1[2 * p] = u.x; r1[2 * p + 1] = u.y;
    }
    float* o0 = out + (size_t)row0 * COUT + yoff;
#pragma unroll
    for (int i = 0; i < SLICE / 4; i++)
        reinterpret_cast<float4*>(o0)[i] = reinterpret_cast<float4*>(r0)[i];
    if (has1) {
        float* o1 = out + (size_t)row1 * COUT + yoff;
#pragma unroll
        for (int i = 0; i < SLICE / 4; i++)
            reinterpret_cast<float4*>(o1)[i] = reinterpret_cast<float4*>(r1)[i];
    }
}

// ---------------------------------------------------------------------------
// First conv: CIN=4 (geo ++ col), COUT=32, K=125, ReLU out.
// ---------------------------------------------------------------------------
__global__ __launch_bounds__(256, 3) void conv1_k(
    const float* __restrict__ geo, const float* __restrict__ col,
    const float* __restrict__ W, const int* __restrict__ in_map, int n_in,
    int n_out, float* __restrict__ out) {
    extern __shared__ float sm[];
    const int tid = threadIdx.x;
    for (int i = tid; i < 125 * 32; i += 256)
        reinterpret_cast<float4*>(sm)[i] = reinterpret_cast<const float4*>(W)[i];
    __syncthreads();

    const int row = blockIdx.x * 256 + tid;
    if (row >= n_out) return;

    ull acc[16];
#pragma unroll
    for (int i = 0; i < 16; i++) acc[i] = 0ull;

    int idxn = __ldg(&in_map[row]);
    for (int k = 0; k < 125; k++) {
        int idx = idxn;
        if (k + 1 < 125) idxn = __ldg(&in_map[(size_t)(k + 1) * n_out + row]);
        if (idx >= n_in) continue;

        float fr[4];
        fr[0] = __ldg(&geo[idx]);
        fr[1] = __ldg(&col[(size_t)idx * 3]);
        fr[2] = __ldg(&col[(size_t)idx * 3 + 1]);
        fr[3] = __ldg(&col[(size_t)idx * 3 + 2]);
        const float* wk = sm + k * 128;
#pragma unroll
        for (int c = 0; c < 4; c++) {
            ull a2 = pack2(fr[c]);
            const ulonglong2* wrow = reinterpret_cast<const ulonglong2*>(wk + c * 32);
#pragma unroll
            for (int p = 0; p < 8; p++) {
                ulonglong2 w = wrow[p];
                fma2(acc[2 * p], a2, w.x);
                fma2(acc[2 * p + 1], a2, w.y);
            }
        }
    }
    float res[32];
#pragma unroll
    for (int p = 0; p < 16; p++) {
        float2 v = *reinterpret_cast<float2*>(&acc[p]);
        res[2 * p] = fmaxf(v.x, 0.f);
        res[2 * p + 1] = fmaxf(v.y, 0.f);
    }
    float* op = out + (size_t)row * 32;
#pragma unroll
    for (int i = 0; i < 8; i++)
        reinterpret_cast<float4*>(op)[i] = reinterpret_cast<float4*>(res)[i];
}

// ---------------------------------------------------------------------------
// BN stats stage 1 (deterministic per-block per-channel partials).
// ---------------------------------------------------------------------------
__global__ __launch_bounds__(256) void bn_stats(const float* __restrict__ z,
                                                int n, int C,
                                                float* __restrict__ part) {
    __shared__ float smr[512];
    const int tid = threadIdx.x;
    float s = 0.f, ss = 0.f;
    int total = n * C;
    for (int i = blockIdx.x * 256 + tid; i < total; i += gridDim.x * 256) {
        float v = z[i];
        s += v;
        ss += v * v;
    }
    smr[tid] = s;
    smr[256 + tid] = ss;
    __syncthreads();
    for (int off = 128; off >= C; off >>= 1) {
        if (tid < off) {
            smr[tid] += smr[tid + off];
            smr[256 + tid] += smr[256 + tid + off];
        }
        __syncthreads();
    }
    if (tid < C) {
        part[((size_t)blockIdx.x * C + tid) * 2] = smr[tid];
        part[((size_t)blockIdx.x * C + tid) * 2 + 1] = smr[256 + tid];
    }
}

// Stage 2: parallel deterministic fold -> scale/shift.
__global__ __launch_bounds__(256) void bn_reduce(
    const float* __restrict__ part, int nblk, int C, int n,
    const float* __restrict__ g, const float* __restrict__ b,
    float* __restrict__ params) {
    __shared__ float ss[256], sq[256];
    const int t = threadIdx.x;
    const int P = 256 / C;
    const int c = t % C, r = t / C;
    float s = 0.f, q = 0.f;
    for (int i = r; i < nblk; i += P) {
        s += part[((size_t)i * C + c) * 2];
        q += part[((size_t)i * C + c) * 2 + 1];
    }
    ss[t] = s;
    sq[t] = q;
    __syncthreads();
    for (int o = P / 2; o >= 1; o >>= 1) {
        if (r < o) {
            ss[t] += ss[t + o * C];
            sq[t] += sq[t + o * C];
        }
        __syncthreads();
    }
    if (r == 0) {
        float inv_n = 1.f / (float)n;
        float mu = ss[t] * inv_n;
        float var = sq[t] * inv_n - mu * mu;
        float sc = g[c] * rsqrtf(var + 1e-5f);
        params[c] = sc;
        params[C + c] = b[c] - mu * sc;
    }
}

// xt = relu(z*scale + shift)
__global__ __launch_bounds__(256) void bn_apply(
    const float4* __restrict__ z, const float* __restrict__ par,
    float4* __restrict__ out, int n, int C) {
    int total = n * C / 4;
    for (int i = blockIdx.x * 256 + threadIdx.x; i < total; i += gridDim.x * 256) {
        int cb = (i * 4) % C;
        float4 v = z[i];
        v.x = fmaxf(v.x * par[cb] + par[C + cb], 0.f);
        v.y = fmaxf(v.y * par[cb + 1] + par[C + cb + 1], 0.f);
        v.z = fmaxf(v.z * par[cb + 2] + par[C + cb + 2], 0.f);
        v.w = fmaxf(v.w * par[cb + 3] + par[C + cb + 3], 0.f);
        out[i] = v;
    }
}

// out = relu(z*scale + shift + res)
__global__ __launch_bounds__(256) void bn_res_relu(
    const float4* __restrict__ z, const float* __restrict__ par,
    const float4* __restrict__ res, float4* __restrict__ out, int n, int C) {
    int total = n * C / 4;
    for (int i = blockIdx.x * 256 + threadIdx.x; i < total; i += gridDim.x * 256) {
        int cb = (i * 4) % C;
        float4 v = z[i];
        float4 r = res[i];
        v.x = fmaxf(v.x * par[cb] + par[C + cb] + r.x, 0.f);
        v.y = fmaxf(v.y * par[cb + 1] + par[C + cb + 1] + r.y, 0.f);
        v.z = fmaxf(v.z * par[cb + 2] + par[C + cb + 2] + r.z, 0.f);
        v.w = fmaxf(v.w * par[cb + 3] + par[C + cb + 3] + r.w, 0.f);
        out[i] = v;
    }
}

// ---------------------------------------------------------------------------
extern "C" void kernel_launch(void* const* d_in, const int* in_sizes, int n_in,
                              void* d_out, int out_size) {
    const float* x_geo = (const float*)d_in[0];
    const float* x_col = (const float*)d_in[1];
    const float* w0 = (const float*)d_in[2];
    const float* w_e1 = (const float*)d_in[3];
    const float* g_e1 = (const float*)d_in[4];
    const float* b_e1 = (const float*)d_in[5];
    const float* w2 = (const float*)d_in[6];
    const float* w_e2 = (const float*)d_in[7];
    const float* g_e2 = (const float*)d_in[8];
    const float* b_e2 = (const float*)d_in[9];
    const int* m1_in = (const int*)d_in[10];
    const int* m2_in = (const int*)d_in[12];
    const int* m3_in = (const int*)d_in[14];
    const int* m4_in = (const int*)d_in[16];

    const int N = in_sizes[0];
    const int n2 = in_sizes[10] / 125;
    const int n4 = in_sizes[14] / 27;

    float *xc, *z1, *z2, *xt, *yb, *part, *par;
    cudaGetSymbolAddress((void**)&xc, g_xc);
    cudaGetSymbolAddress((void**)&z1, g_z1);
    cudaGetSymbolAddress((void**)&z2, g_z2);
    cudaGetSymbolAddress((void**)&xt, g_xt);
    cudaGetSymbolAddress((void**)&yb, g_y);
    cudaGetSymbolAddress((void**)&part, g_part);
    cudaGetSymbolAddress((void**)&par, g_par);

    const int SM1 = 125 * 4 * 32 * 4;        // 64000
    const int SME1 = 27 * 32 * 16 * 4;       // 55296 (CIN=32, SLICE=16)
    const int SMC2 = 27 * 32 * 8 * 4;        // 27648 (CIN=32, SLICE=8)
    const int SME2 = 27 * 64 * 8 * 4;        // 55296 (CIN=64, SLICE=8)
    cudaFuncSetAttribute(conv1_k, cudaFuncAttributeMaxDynamicSharedMemorySize, SM1);
    cudaFuncSetAttribute(conv2_t<32, 16>, cudaFuncAttributeMaxDynamicSharedMemorySize, SME1);
    cudaFuncSetAttribute(conv2_t<32, 8>, cudaFuncAttributeMaxDynamicSharedMemorySize, SMC2);
    cudaFuncSetAttribute(conv2_t<64, 8>, cudaFuncAttributeMaxDynamicSharedMemorySize, SME2);

    const int gc1 = (n2 + 255) / 256;
    const dim3 ge1((n2 + 511) / 512, 2);    // 32ch out, SLICE 16
    const dim3 gc2((n4 + 511) / 512, 8);    // 64ch out, SLICE 8
    const dim3 ge2((n4 + 511) / 512, 8);    // 64ch out, SLICE 8
    const int eg2 = (n2 * 32 / 4 + 255) / 256;
    const int eg4 = (n4 * 64 / 4 + 255) / 256;

    // conv1 (k5 s2, 4->32) + ReLU
    conv1_k<<<gc1, 256, SM1>>>(x_geo, x_col, w0, m1_in, N, n2, xc);

    // enc1: 2 BasicBlocks, 32ch
    for (int i = 0; i < 2; i++) {
        const float* wA = w_e1 + (size_t)(i * 2 + 0) * 27 * 32 * 32;
        const float* wB = w_e1 + (size_t)(i * 2 + 1) * 27 * 32 * 32;
        conv2_t<32, 16><<<ge1, 256, SME1>>>(xc, wA, m2_in, 27, n2, n2, 32, z1);
        bn_stats<<<STATS_BLOCKS, 256>>>(z1, n2, 32, part);
        bn_reduce<<<1, 256>>>(part, STATS_BLOCKS, 32, n2,
                              g_e1 + (size_t)(i * 2) * 32, b_e1 + (size_t)(i * 2) * 32, par);
        bn_apply<<<eg2 < 2048 ? eg2 : 2048, 256>>>((const float4*)z1, par, (float4*)xt, n2, 32);
        conv2_t<32, 16><<<ge1, 256, SME1>>>(xt, wB, m2_in, 27, n2, n2, 32, z2);
        bn_stats<<<STATS_BLOCKS, 256>>>(z2, n2, 32, part);
        bn_reduce<<<1, 256>>>(part, STATS_BLOCKS, 32, n2,
                              g_e1 + (size_t)(i * 2 + 1) * 32, b_e1 + (size_t)(i * 2 + 1) * 32, par);
        bn_res_relu<<<eg2 < 2048 ? eg2 : 2048, 256>>>(
            (const float4*)z2, par, (const float4*)xc, (float4*)xc, n2, 32);
    }

    // conv2 (32 -> 64, onto stride-4 coords)
    conv2_t<32, 8><<<gc2, 256, SMC2>>>(xc, w2, m3_in, 27, n2, n4, 64, yb);

    // enc2: 2 BasicBlocks, 64ch
    for (int i = 0; i < 2; i++) {
        const float* wA = w_e2 + (size_t)(i * 2 + 0) * 27 * 64 * 64;
        const float* wB = w_e2 + (size_t)(i * 2 + 1) * 27 * 64 * 64;
        conv2_t<64, 8><<<ge2, 256, SME2>>>(yb, wA, m4_in, 27, n4, n4, 64, z1);
        bn_stats<<<STATS_BLOCKS, 256>>>(z1, n4, 64, part);
        bn_reduce<<<1, 256>>>(part, STATS_BLOCKS, 64, n4,
                              g_e2 + (size_t)(i * 2) * 64, b_e2 + (size_t)(i * 2) * 64, par);
        bn_apply<<<eg4 < 2048 ? eg4 : 2048, 256>>>((const float4*)z1, par, (float4*)xt, n4, 64);
        conv2_t<64, 8><<<ge2, 256, SME2>>>(xt, wB, m4_in, 27, n4, n4, 64, z2);
        bn_stats<<<STATS_BLOCKS, 256>>>(z2, n4, 64, part);
        bn_reduce<<<1, 256>>>(part, STATS_BLOCKS, 64, n4,
                              g_e2 + (size_t)(i * 2 + 1) * 64, b_e2 + (size_t)(i * 2 + 1) * 64, par);
        float* dst = (i == 1) ? (float*)d_out : yb;
        bn_res_relu<<<eg4 < 2048 ? eg4 : 2048, 256>>>(
            (const float4*)z2, par, (const float4*)yb, (float4*)dst, n4, 64);
    }
}